// round 10
// baseline (speedup 1.0000x reference)
#include <cuda_runtime.h>
#include <stdint.h>
#include <math.h>

#define NB        50
#define NF_DIST   1225
#define NF_ANG    48
#define NF_DIH    47
#define NFEAT     (NF_DIST + NF_ANG + 2*NF_DIH)   // 1367

#define OFF_ANG   NF_DIST                 // 1225
#define OFF_DCOS  (NF_DIST + NF_ANG)      // 1273
#define OFF_DSIN  (OFF_DCOS + NF_DIH)     // 1320

// 7 groups of 7 rows: inc0 = 7g+1, tasks per group = 50 - inc0. Total 196.
#define NTASK     196
#define T_ANG0    196
#define T_DIH0    (T_ANG0 + NF_ANG)       // 244
#define T_END     (T_DIH0 + NF_DIH)       // 291
#define NTHREADS  320
#define FPB       4                        // frames per block

struct TaskTable { uint32_t v[NTASK]; };
constexpr TaskTable make_tasks() {
    TaskTable t{};
    int n = 0;
    for (int g = 0; g < 7; ++g) {
        const int inc0 = 7 * g + 1;
        const int f0   = (inc0 - 1) * (100 - inc0) / 2;
        for (int i = 0; i < NB - inc0; ++i)
            t.v[n++] = (uint32_t)(i | (inc0 << 6) | (f0 << 12));
    }
    return t;
}
__device__ constexpr TaskTable g_tasks = make_tasks();

typedef unsigned long long u64;
__device__ __forceinline__ u64 f2_pack(float lo, float hi) {
    u64 r; asm("mov.b64 %0, {%1, %2};" : "=l"(r) : "f"(lo), "f"(hi)); return r;
}
__device__ __forceinline__ u64 f2_packr(unsigned lo, unsigned hi) {
    u64 r; asm("mov.b64 %0, {%1, %2};" : "=l"(r) : "r"(lo), "r"(hi)); return r;
}
__device__ __forceinline__ void f2_unpack(float& lo, float& hi, u64 v) {
    asm("mov.b64 {%0, %1}, %2;" : "=f"(lo), "=f"(hi) : "l"(v));
}
__device__ __forceinline__ u64 f2_add(u64 a, u64 b) {
    u64 r; asm("add.rn.f32x2 %0, %1, %2;" : "=l"(r) : "l"(a), "l"(b)); return r;
}
__device__ __forceinline__ u64 f2_mul(u64 a, u64 b) {
    u64 r; asm("mul.rn.f32x2 %0, %1, %2;" : "=l"(r) : "l"(a), "l"(b)); return r;
}
__device__ __forceinline__ u64 f2_fma(u64 a, u64 b, u64 c) {
    u64 r; asm("fma.rn.f32x2 %0, %1, %2, %3;" : "=l"(r) : "l"(a), "l"(b), "l"(c)); return r;
}
__device__ __forceinline__ float fast_sqrt(float x) {
    float r; asm("sqrt.approx.f32 %0, %1;" : "=f"(r) : "f"(x)); return r;
}

__shared__ float4 sX[NB], sY[NB], sZ[NB];   // per-coord, 4 frames packed

// Distance sweep; offsets are per-frame output deltas (in floats).
__device__ __forceinline__ void dist_sweep(uint32_t tv, float* __restrict__ o0,
                                           int off1, int off2, int off3)
{
    const int i    = tv & 63;
    const int inc0 = (tv >> 6) & 63;
    const int rl   = NB - inc0;
    int f          = (int)(tv >> 12) + i;
    int j          = i + inc0;

    const float4 Ax = sX[i], Ay = sY[i], Az = sZ[i];
    const u64 nax01 = f2_pack(-Ax.x, -Ax.y), nax23 = f2_pack(-Ax.z, -Ax.w);
    const u64 nay01 = f2_pack(-Ay.x, -Ay.y), nay23 = f2_pack(-Ay.z, -Ay.w);
    const u64 naz01 = f2_pack(-Az.x, -Az.y), naz23 = f2_pack(-Az.z, -Az.w);

    #pragma unroll
    for (int k = 0; k < 7; ++k) {
        if (j < NB) {
            const uint4 vx = *reinterpret_cast<const uint4*>(&sX[j]);
            const uint4 vy = *reinterpret_cast<const uint4*>(&sY[j]);
            const uint4 vz = *reinterpret_cast<const uint4*>(&sZ[j]);

            const u64 dx01 = f2_add(f2_packr(vx.x, vx.y), nax01);
            const u64 dx23 = f2_add(f2_packr(vx.z, vx.w), nax23);
            const u64 dy01 = f2_add(f2_packr(vy.x, vy.y), nay01);
            const u64 dy23 = f2_add(f2_packr(vy.z, vy.w), nay23);
            const u64 dz01 = f2_add(f2_packr(vz.x, vz.y), naz01);
            const u64 dz23 = f2_add(f2_packr(vz.z, vz.w), naz23);

            const u64 s01 = f2_fma(dx01, dx01, f2_fma(dy01, dy01, f2_mul(dz01, dz01)));
            const u64 s23 = f2_fma(dx23, dx23, f2_fma(dy23, dy23, f2_mul(dz23, dz23)));

            float s0, s1, s2, s3;
            f2_unpack(s0, s1, s01);
            f2_unpack(s2, s3, s23);

            float* po = o0 + f;
            po[0]    = fast_sqrt(s0);
            po[off1] = fast_sqrt(s1);
            po[off2] = fast_sqrt(s2);
            po[off3] = fast_sqrt(s3);
        }
        f += rl - k;
        ++j;
    }
}

__global__ __launch_bounds__(NTHREADS)
void protein_feat_kernel(const float* __restrict__ data,
                         float* __restrict__ out,
                         int n_frames)
{
    const int tid    = threadIdx.x;
    const int frame0 = blockIdx.x * FPB;
    const int nrem   = n_frames - frame0;        // >= 1

    // ---- stage 4 frames (600 floats), clamped ----
    for (int t = tid; t < NB * 3 * FPB; t += NTHREADS) {
        const int fr = t / (NB * 3);
        const int r  = t - fr * (NB * 3);
        const int bd = r / 3;
        const int c  = r - 3 * bd;
        const int src = (fr < nrem) ? fr : (nrem - 1);
        const float v = data[(size_t)(frame0 + src) * (NB * 3) + r];
        float* dst = (c == 0) ? (float*)sX : (c == 1) ? (float*)sY : (float*)sZ;
        dst[4 * bd + fr] = v;
    }
    __syncthreads();

    float* o0 = out + (size_t)frame0 * NFEAT;
    const bool full = (nrem >= FPB);

    if (tid < NTASK) {
        const uint32_t tv = g_tasks.v[tid];
        if (full) {
            dist_sweep(tv, o0, NFEAT, 2 * NFEAT, 3 * NFEAT);   // immediate offsets
        } else {
            const int m = nrem - 1;
            dist_sweep(tv, o0,
                       (1 < nrem ? 1 : m) * NFEAT,
                       (2 < nrem ? 2 : m) * NFEAT,
                       m * NFEAT);
        }
    }
    else if (tid < T_DIH0) {
        // ---- angles, 4 frames scalar ----
        const int a = tid - T_ANG0;
        const float* fx = (const float*)sX;
        const float* fy = (const float*)sY;
        const float* fz = (const float*)sZ;
        #pragma unroll
        for (int fr = 0; fr < FPB; ++fr) {
            const int a0 = 4 * a + fr, a1 = a0 + 4, a2 = a0 + 8;
            const float b1x = fx[a0] - fx[a1];
            const float b1y = fy[a0] - fy[a1];
            const float b1z = fz[a0] - fz[a1];
            const float b2x = fx[a2] - fx[a1];
            const float b2y = fy[a2] - fy[a1];
            const float b2z = fz[a2] - fz[a1];

            const float dot = fmaf(b1x, b2x, fmaf(b1y, b2y, b1z * b2z));
            const float n1  = fmaf(b1x, b1x, fmaf(b1y, b1y, b1z * b1z));
            const float n2  = fmaf(b2x, b2x, fmaf(b2y, b2y, b2z * b2z));
            float ct = dot * rsqrtf(n1 * n2);
            ct = fminf(1.0f, fmaxf(-1.0f, ct));
            const int off = ((fr < nrem) ? fr : (nrem - 1)) * NFEAT;
            o0[off + OFF_ANG + a] = acosf(ct);
        }
    }
    else if (tid < T_END) {
        // ---- dihedrals (cos+sin fused), 4 frames scalar ----
        const int d = tid - T_DIH0;
        const float* fx = (const float*)sX;
        const float* fy = (const float*)sY;
        const float* fz = (const float*)sZ;
        #pragma unroll
        for (int fr = 0; fr < FPB; ++fr) {
            const int d0 = 4 * d + fr, d1 = d0 + 4, d2 = d0 + 8, d3 = d0 + 12;

            const float ax = fx[d1] - fx[d0], ay = fy[d1] - fy[d0], az = fz[d1] - fz[d0];
            const float bx = fx[d2] - fx[d1], by = fy[d2] - fy[d1], bz = fz[d2] - fz[d1];
            const float cx = fx[d3] - fx[d2], cy = fy[d3] - fy[d2], cz = fz[d3] - fz[d2];

            const float p1x = ay * bz - az * by;
            const float p1y = az * bx - ax * bz;
            const float p1z = ax * by - ay * bx;
            const float p2x = by * cz - bz * cy;
            const float p2y = bz * cx - bx * cz;
            const float p2z = bx * cy - by * cx;

            const float n1sq  = fmaf(p1x, p1x, fmaf(p1y, p1y, p1z * p1z));
            const float n2sq  = fmaf(p2x, p2x, fmaf(p2y, p2y, p2z * p2z));
            const float inv12 = rsqrtf(n1sq * n2sq);

            const int off = ((fr < nrem) ? fr : (nrem - 1)) * NFEAT;
            float* oo = o0 + off;
            const float dp = fmaf(p1x, p2x, fmaf(p1y, p2y, p1z * p2z));
            oo[OFF_DCOS + d] = dp * inv12;

            const float qx = p1y * p2z - p1z * p2y;
            const float qy = p1z * p2x - p1x * p2z;
            const float qz = p1x * p2y - p1y * p2x;
            const float num  = fmaf(qx, bx, fmaf(qy, by, qz * bz));
            const float bnsq = fmaf(bx, bx, fmaf(by, by, bz * bz));
            oo[OFF_DSIN + d] = num * inv12 * rsqrtf(bnsq);
        }
    }
}

extern "C" void kernel_launch(void* const* d_in, const int* in_sizes, int n_in,
                              void* d_out, int out_size)
{
    const float* data = (const float*)d_in[0];
    float* out = (float*)d_out;
    const int n_frames = in_sizes[0] / (NB * 3);
    const int n_blocks = (n_frames + FPB - 1) / FPB;

    protein_feat_kernel<<<n_blocks, NTHREADS>>>(data, out, n_frames);
}

// round 11
// speedup vs baseline: 1.0355x; 1.0355x over previous
#include <cuda_runtime.h>
#include <stdint.h>
#include <math.h>

#define NB        50
#define NF_DIST   1225
#define NF_ANG    48
#define NF_DIH    47
#define NFEAT     (NF_DIST + NF_ANG + 2*NF_DIH)   // 1367

#define OFF_ANG   NF_DIST                 // 1225
#define OFF_DCOS  (NF_DIST + NF_ANG)      // 1273
#define OFF_DSIN  (OFF_DCOS + NF_DIH)     // 1320

// 7 groups of 7 rows: inc0 = 7g+1, tasks per group = 50 - inc0. Total 196.
#define NTASK     196
#define T_ANG0    196
#define T_DIH0    (T_ANG0 + NF_ANG)       // 244
#define T_END     (T_DIH0 + NF_DIH)       // 291
#define NTHREADS  320
#define FPB       4                        // frames per block (hot kernel)

struct TaskTable { uint32_t v[NTASK]; };
constexpr TaskTable make_tasks() {
    TaskTable t{};
    int n = 0;
    for (int g = 0; g < 7; ++g) {
        const int inc0 = 7 * g + 1;
        const int f0   = (inc0 - 1) * (100 - inc0) / 2;
        for (int i = 0; i < NB - inc0; ++i)
            t.v[n++] = (uint32_t)(i | (inc0 << 6) | (f0 << 12));
    }
    return t;
}
__device__ constexpr TaskTable g_tasks = make_tasks();

typedef unsigned long long u64;
__device__ __forceinline__ u64 f2_pack(float lo, float hi) {
    u64 r; asm("mov.b64 %0, {%1, %2};" : "=l"(r) : "f"(lo), "f"(hi)); return r;
}
__device__ __forceinline__ void f2_unpack(float& lo, float& hi, u64 v) {
    asm("mov.b64 {%0, %1}, %2;" : "=f"(lo), "=f"(hi) : "l"(v));
}
__device__ __forceinline__ u64 f2_add(u64 a, u64 b) {
    u64 r; asm("add.rn.f32x2 %0, %1, %2;" : "=l"(r) : "l"(a), "l"(b)); return r;
}
__device__ __forceinline__ u64 f2_mul(u64 a, u64 b) {
    u64 r; asm("mul.rn.f32x2 %0, %1, %2;" : "=l"(r) : "l"(a), "l"(b)); return r;
}
__device__ __forceinline__ u64 f2_fma(u64 a, u64 b, u64 c) {
    u64 r; asm("fma.rn.f32x2 %0, %1, %2, %3;" : "=l"(r) : "l"(a), "l"(b), "l"(c)); return r;
}
__device__ __forceinline__ float fast_sqrt(float x) {
    float r; asm("sqrt.approx.f32 %0, %1;" : "=f"(r) : "f"(x)); return r;
}
// LDS.128 -> two u64 (frames 0-1, 2-3) directly
__device__ __forceinline__ void lds_v2b64(u64& a, u64& b, const void* p) {
    unsigned addr = (unsigned)__cvta_generic_to_shared(p);
    asm("ld.shared.v2.b64 {%0, %1}, [%2];" : "=l"(a), "=l"(b) : "r"(addr));
}

// Hot-kernel shared tiles: per-coordinate, 4 frames packed in float4.
__shared__ float4 sX[NB], sY[NB], sZ[NB];

__global__ __launch_bounds__(NTHREADS, 4)
void protein_feat_kernel4(const float* __restrict__ data,
                          float* __restrict__ out)
{
    const int tid    = threadIdx.x;
    const int frame0 = blockIdx.x * FPB;

    // ---- stage 4 full frames (600 floats) ----
    for (int t = tid; t < NB * 3 * FPB; t += NTHREADS) {
        const int fr = t / (NB * 3);
        const int r  = t - fr * (NB * 3);
        const int bd = r / 3;
        const int c  = r - 3 * bd;
        const float v = data[(size_t)(frame0 + fr) * (NB * 3) + r];
        float* dst = (c == 0) ? (float*)sX : (c == 1) ? (float*)sY : (float*)sZ;
        dst[4 * bd + fr] = v;
    }
    __syncthreads();

    float* o0 = out + (size_t)frame0 * NFEAT;

    if (tid < NTASK) {
        // ---- distances: pair (i, j..j+6) for 4 frames ----
        const uint32_t tv = g_tasks.v[tid];
        const int i    = tv & 63;
        const int inc0 = (tv >> 6) & 63;
        const int rl   = NB - inc0;
        int f          = (int)(tv >> 12) + i;
        int j          = i + inc0;

        const float4 Ax = sX[i], Ay = sY[i], Az = sZ[i];
        const u64 nax01 = f2_pack(-Ax.x, -Ax.y), nax23 = f2_pack(-Ax.z, -Ax.w);
        const u64 nay01 = f2_pack(-Ay.x, -Ay.y), nay23 = f2_pack(-Ay.z, -Ay.w);
        const u64 naz01 = f2_pack(-Az.x, -Az.y), naz23 = f2_pack(-Az.z, -Az.w);

        #pragma unroll
        for (int k = 0; k < 7; ++k) {
            if (j < NB) {
                u64 bx01, bx23, by01, by23, bz01, bz23;
                lds_v2b64(bx01, bx23, &sX[j]);
                lds_v2b64(by01, by23, &sY[j]);
                lds_v2b64(bz01, bz23, &sZ[j]);

                const u64 dx01 = f2_add(bx01, nax01);
                const u64 dx23 = f2_add(bx23, nax23);
                const u64 dy01 = f2_add(by01, nay01);
                const u64 dy23 = f2_add(by23, nay23);
                const u64 dz01 = f2_add(bz01, naz01);
                const u64 dz23 = f2_add(bz23, naz23);

                const u64 s01 = f2_fma(dx01, dx01, f2_fma(dy01, dy01, f2_mul(dz01, dz01)));
                const u64 s23 = f2_fma(dx23, dx23, f2_fma(dy23, dy23, f2_mul(dz23, dz23)));

                float s0, s1, s2, s3;
                f2_unpack(s0, s1, s01);
                f2_unpack(s2, s3, s23);

                float* po = o0 + f;
                po[0]         = fast_sqrt(s0);
                po[NFEAT]     = fast_sqrt(s1);
                po[2 * NFEAT] = fast_sqrt(s2);
                po[3 * NFEAT] = fast_sqrt(s3);
            }
            f += rl - k;
            ++j;
        }
    }
    else if (tid < T_DIH0) {
        // ---- angles, 4 frames scalar ----
        const int a = tid - T_ANG0;
        const float* fx = (const float*)sX;
        const float* fy = (const float*)sY;
        const float* fz = (const float*)sZ;
        #pragma unroll
        for (int fr = 0; fr < FPB; ++fr) {
            const int a0 = 4 * a + fr, a1 = a0 + 4, a2 = a0 + 8;
            const float b1x = fx[a0] - fx[a1];
            const float b1y = fy[a0] - fy[a1];
            const float b1z = fz[a0] - fz[a1];
            const float b2x = fx[a2] - fx[a1];
            const float b2y = fy[a2] - fy[a1];
            const float b2z = fz[a2] - fz[a1];

            const float dot = fmaf(b1x, b2x, fmaf(b1y, b2y, b1z * b2z));
            const float n1  = fmaf(b1x, b1x, fmaf(b1y, b1y, b1z * b1z));
            const float n2  = fmaf(b2x, b2x, fmaf(b2y, b2y, b2z * b2z));
            float ct = dot * rsqrtf(n1 * n2);
            ct = fminf(1.0f, fmaxf(-1.0f, ct));
            o0[fr * NFEAT + OFF_ANG + a] = acosf(ct);
        }
    }
    else if (tid < T_END) {
        // ---- dihedrals (cos+sin fused), 4 frames scalar ----
        const int d = tid - T_DIH0;
        const float* fx = (const float*)sX;
        const float* fy = (const float*)sY;
        const float* fz = (const float*)sZ;
        #pragma unroll
        for (int fr = 0; fr < FPB; ++fr) {
            const int d0 = 4 * d + fr, d1 = d0 + 4, d2 = d0 + 8, d3 = d0 + 12;

            const float ax = fx[d1] - fx[d0], ay = fy[d1] - fy[d0], az = fz[d1] - fz[d0];
            const float bx = fx[d2] - fx[d1], by = fy[d2] - fy[d1], bz = fz[d2] - fz[d1];
            const float cx = fx[d3] - fx[d2], cy = fy[d3] - fy[d2], cz = fz[d3] - fz[d2];

            const float p1x = ay * bz - az * by;
            const float p1y = az * bx - ax * bz;
            const float p1z = ax * by - ay * bx;
            const float p2x = by * cz - bz * cy;
            const float p2y = bz * cx - bx * cz;
            const float p2z = bx * cy - by * cx;

            const float n1sq  = fmaf(p1x, p1x, fmaf(p1y, p1y, p1z * p1z));
            const float n2sq  = fmaf(p2x, p2x, fmaf(p2y, p2y, p2z * p2z));
            const float inv12 = rsqrtf(n1sq * n2sq);

            float* oo = o0 + fr * NFEAT;
            const float dp = fmaf(p1x, p2x, fmaf(p1y, p2y, p1z * p2z));
            oo[OFF_DCOS + d] = dp * inv12;

            const float qx = p1y * p2z - p1z * p2y;
            const float qy = p1z * p2x - p1x * p2z;
            const float qz = p1x * p2y - p1y * p2x;
            const float num  = fmaf(qx, bx, fmaf(qy, by, qz * bz));
            const float bnsq = fmaf(bx, bx, fmaf(by, by, bz * bz));
            oo[OFF_DSIN + d] = num * inv12 * rsqrtf(bnsq);
        }
    }
}

// ---- tail: one frame per block (cold path; empty grid when n%4==0) ----
__global__ __launch_bounds__(NTHREADS)
void protein_feat_kernel1(const float* __restrict__ data,
                          float* __restrict__ out,
                          int frame_base)
{
    __shared__ float tx[NB], ty[NB], tz[NB];

    const int tid   = threadIdx.x;
    const int frame = frame_base + blockIdx.x;

    const float* p = data + (size_t)frame * NB * 3;
    if (tid < NB * 3) {
        const int bd = tid / 3, c = tid - 3 * bd;
        const float v = p[tid];
        if (c == 0) tx[bd] = v; else if (c == 1) ty[bd] = v; else tz[bd] = v;
    }
    __syncthreads();

    float* o = out + (size_t)frame * NFEAT;

    if (tid < NTASK) {
        const uint32_t tv = g_tasks.v[tid];
        const int i    = tv & 63;
        const int inc0 = (tv >> 6) & 63;
        const int rl   = NB - inc0;
        int f          = (int)(tv >> 12) + i;
        int j          = i + inc0;
        const float ax = tx[i], ay = ty[i], az = tz[i];

        #pragma unroll
        for (int k = 0; k < 7; ++k) {
            if (j < NB) {
                const float dx = tx[j] - ax;
                const float dy = ty[j] - ay;
                const float dz = tz[j] - az;
                o[f] = fast_sqrt(fmaf(dx, dx, fmaf(dy, dy, dz * dz)));
            }
            f += rl - k;
            ++j;
        }
    }
    else if (tid < T_DIH0) {
        const int a = tid - T_ANG0;
        const float b1x = tx[a] - tx[a+1], b1y = ty[a] - ty[a+1], b1z = tz[a] - tz[a+1];
        const float b2x = tx[a+2] - tx[a+1], b2y = ty[a+2] - ty[a+1], b2z = tz[a+2] - tz[a+1];
        const float dot = fmaf(b1x, b2x, fmaf(b1y, b2y, b1z * b2z));
        const float n1  = fmaf(b1x, b1x, fmaf(b1y, b1y, b1z * b1z));
        const float n2  = fmaf(b2x, b2x, fmaf(b2y, b2y, b2z * b2z));
        float ct = dot * rsqrtf(n1 * n2);
        ct = fminf(1.0f, fmaxf(-1.0f, ct));
        o[OFF_ANG + a] = acosf(ct);
    }
    else if (tid < T_END) {
        const int d = tid - T_DIH0;
        const float ax = tx[d+1]-tx[d], ay = ty[d+1]-ty[d], az = tz[d+1]-tz[d];
        const float bx = tx[d+2]-tx[d+1], by = ty[d+2]-ty[d+1], bz = tz[d+2]-tz[d+1];
        const float cx = tx[d+3]-tx[d+2], cy = ty[d+3]-ty[d+2], cz = tz[d+3]-tz[d+2];

        const float p1x = ay*bz - az*by, p1y = az*bx - ax*bz, p1z = ax*by - ay*bx;
        const float p2x = by*cz - bz*cy, p2y = bz*cx - bx*cz, p2z = bx*cy - by*cx;

        const float n1sq  = fmaf(p1x, p1x, fmaf(p1y, p1y, p1z * p1z));
        const float n2sq  = fmaf(p2x, p2x, fmaf(p2y, p2y, p2z * p2z));
        const float inv12 = rsqrtf(n1sq * n2sq);

        const float dp = fmaf(p1x, p2x, fmaf(p1y, p2y, p1z * p2z));
        o[OFF_DCOS + d] = dp * inv12;

        const float qx = p1y*p2z - p1z*p2y, qy = p1z*p2x - p1x*p2z, qz = p1x*p2y - p1y*p2x;
        const float num  = fmaf(qx, bx, fmaf(qy, by, qz * bz));
        const float bnsq = fmaf(bx, bx, fmaf(by, by, bz * bz));
        o[OFF_DSIN + d] = num * inv12 * rsqrtf(bnsq);
    }
}

extern "C" void kernel_launch(void* const* d_in, const int* in_sizes, int n_in,
                              void* d_out, int out_size)
{
    const float* data = (const float*)d_in[0];
    float* out = (float*)d_out;
    const int n_frames = in_sizes[0] / (NB * 3);
    const int n4  = n_frames / FPB;
    const int rem = n_frames - n4 * FPB;

    if (n4 > 0)
        protein_feat_kernel4<<<n4, NTHREADS>>>(data, out);
    if (rem > 0)
        protein_feat_kernel1<<<rem, NTHREADS>>>(data, out, n4 * FPB);
}

// round 12
// speedup vs baseline: 1.1557x; 1.1161x over previous
#include <cuda_runtime.h>
#include <stdint.h>
#include <math.h>

#define NB        50
#define NF_DIST   1225
#define NF_ANG    48
#define NF_DIH    47
#define NFEAT     (NF_DIST + NF_ANG + 2*NF_DIH)   // 1367

#define OFF_ANG   NF_DIST                 // 1225
#define OFF_DCOS  (NF_DIST + NF_ANG)      // 1273
#define OFF_DSIN  (OFF_DCOS + NF_DIH)     // 1320

// 7 groups of 7 rows: inc0 = 7g+1, tasks per group = 50 - inc0. Total 196.
#define NTASK     196
#define T_ANG0    196
#define T_DIH0    (T_ANG0 + NF_ANG)       // 244
#define T_END     (T_DIH0 + NF_DIH)       // 291
#define NTHREADS  320

struct TaskTable { uint32_t v[NTASK]; };
constexpr TaskTable make_tasks() {
    TaskTable t{};
    int n = 0;
    for (int g = 0; g < 7; ++g) {
        const int inc0 = 7 * g + 1;
        const int f0   = (inc0 - 1) * (100 - inc0) / 2;
        for (int i = 0; i < NB - inc0; ++i)
            t.v[n++] = (uint32_t)(i | (inc0 << 6) | (f0 << 12));
    }
    return t;
}
__device__ constexpr TaskTable g_tasks = make_tasks();

typedef unsigned long long u64;
__device__ __forceinline__ u64 f2_pack(float lo, float hi) {
    u64 r; asm("mov.b64 %0, {%1, %2};" : "=l"(r) : "f"(lo), "f"(hi)); return r;
}
__device__ __forceinline__ void f2_unpack(float& lo, float& hi, u64 v) {
    asm("mov.b64 {%0, %1}, %2;" : "=f"(lo), "=f"(hi) : "l"(v));
}
__device__ __forceinline__ u64 f2_add(u64 a, u64 b) {
    u64 r; asm("add.rn.f32x2 %0, %1, %2;" : "=l"(r) : "l"(a), "l"(b)); return r;
}
__device__ __forceinline__ u64 f2_mul(u64 a, u64 b) {
    u64 r; asm("mul.rn.f32x2 %0, %1, %2;" : "=l"(r) : "l"(a), "l"(b)); return r;
}
__device__ __forceinline__ u64 f2_fma(u64 a, u64 b, u64 c) {
    u64 r; asm("fma.rn.f32x2 %0, %1, %2, %3;" : "=l"(r) : "l"(a), "l"(b), "l"(c)); return r;
}
__device__ __forceinline__ float fast_sqrt(float x) {
    float r; asm("sqrt.approx.f32 %0, %1;" : "=f"(r) : "f"(x)); return r;
}
// LDS.128 -> two u64: {x_f0,x_f1} and {y_f0,y_f1}
__device__ __forceinline__ void lds_v2b64(u64& a, u64& b, const void* p) {
    unsigned addr = (unsigned)__cvta_generic_to_shared(p);
    asm("ld.shared.v2.b64 {%0, %1}, [%2];" : "=l"(a), "=l"(b) : "r"(addr));
}
__device__ __forceinline__ u64 lds_b64(const void* p) {
    unsigned addr = (unsigned)__cvta_generic_to_shared(p);
    u64 r; asm("ld.shared.b64 %0, [%1];" : "=l"(r) : "r"(addr)); return r;
}

__global__ __launch_bounds__(NTHREADS, 6)
void protein_feat_kernel(const float* __restrict__ data,
                         float* __restrict__ out,
                         int n_frames)
{
    // Per bead: sXY = {x_f0, x_f1, y_f0, y_f1}, sZ = {z_f0, z_f1}
    __shared__ float4 sXY[NB];
    __shared__ float2 sZ[NB];

    const int tid    = threadIdx.x;
    const int frame0 = blockIdx.x * 2;
    const int frame1 = (frame0 + 1 < n_frames) ? frame0 + 1 : frame0; // clamp

    // ---- stage both frames (300 floats) ----
    if (tid < 300) {
        const int fr = (tid >= 150);
        const int r  = tid - 150 * fr;
        const int bd = r / 3;
        const int c  = r - 3 * bd;
        const float v = data[(size_t)(fr ? frame1 : frame0) * (NB * 3) + r];
        if (c == 2)      ((float*)&sZ[bd])[fr]      = v;
        else             ((float*)&sXY[bd])[2*c+fr] = v;
    }
    __syncthreads();

    float* o0 = out + (size_t)frame0 * NFEAT;
    const int o1off = (int)((frame1 - frame0) * NFEAT);   // NFEAT or 0

    if (tid < NTASK) {
        const uint32_t tv = g_tasks.v[tid];
        const int i       = tv & 63;
        const int inc0    = (tv >> 6) & 63;
        const int rl      = NB - inc0;
        int f             = (int)(tv >> 12) + i;
        int j             = i + inc0;

        // negated A bead, packed (both frames)
        const float4 Axy = sXY[i];
        const float2 Az  = sZ[i];
        const u64 nax = f2_pack(-Axy.x, -Axy.y);
        const u64 nay = f2_pack(-Axy.z, -Axy.w);
        const u64 naz = f2_pack(-Az.x,  -Az.y);

        #pragma unroll
        for (int k = 0; k < 7; ++k) {
            if (j < NB) {
                u64 bx, by;
                lds_v2b64(bx, by, &sXY[j]);
                const u64 bz = lds_b64(&sZ[j]);

                const u64 dx = f2_add(bx, nax);
                const u64 dy = f2_add(by, nay);
                const u64 dz = f2_add(bz, naz);

                const u64 s2 = f2_fma(dx, dx, f2_fma(dy, dy, f2_mul(dz, dz)));
                float s0, s1; f2_unpack(s0, s1, s2);

                float* po = o0 + f;
                po[0]     = fast_sqrt(s0);
                po[o1off] = fast_sqrt(s1);
            }
            f += rl - k;
            ++j;
        }
    }
    else if (tid < T_DIH0) {
        // ---- angles, both frames (scalar) ----
        const int a = tid - T_ANG0;
        const float* fxy = (const float*)sXY;   // [4b+0/1]=x, [4b+2/3]=y
        const float* fz  = (const float*)sZ;    // [2b+fr]=z
        #pragma unroll
        for (int fr = 0; fr < 2; ++fr) {
            const int b0 = 4*a + fr, b1 = b0 + 4, b2 = b0 + 8;
            const int z0 = 2*a + fr, z1 = z0 + 2, z2 = z0 + 4;
            const float b1x = fxy[b0]   - fxy[b1];
            const float b1y = fxy[b0+2] - fxy[b1+2];
            const float b1z = fz[z0]    - fz[z1];
            const float b2x = fxy[b2]   - fxy[b1];
            const float b2y = fxy[b2+2] - fxy[b1+2];
            const float b2z = fz[z2]    - fz[z1];

            const float dot = fmaf(b1x, b2x, fmaf(b1y, b2y, b1z * b2z));
            const float n1  = fmaf(b1x, b1x, fmaf(b1y, b1y, b1z * b1z));
            const float n2  = fmaf(b2x, b2x, fmaf(b2y, b2y, b2z * b2z));
            float ct = dot * rsqrtf(n1 * n2);
            ct = fminf(1.0f, fmaxf(-1.0f, ct));
            o0[fr * o1off + OFF_ANG + a] = acosf(ct);
        }
    }
    else if (tid < T_END) {
        // ---- dihedrals (cos+sin fused), both frames (scalar) ----
        const int d = tid - T_DIH0;
        const float* fxy = (const float*)sXY;
        const float* fz  = (const float*)sZ;
        #pragma unroll
        for (int fr = 0; fr < 2; ++fr) {
            const int b0 = 4*d + fr, b1 = b0 + 4, b2 = b0 + 8, b3 = b0 + 12;
            const int z0 = 2*d + fr, z1 = z0 + 2, z2 = z0 + 4, z3 = z0 + 6;

            const float ax = fxy[b1]   - fxy[b0];
            const float ay = fxy[b1+2] - fxy[b0+2];
            const float az = fz[z1]    - fz[z0];
            const float bx = fxy[b2]   - fxy[b1];
            const float by = fxy[b2+2] - fxy[b1+2];
            const float bz = fz[z2]    - fz[z1];
            const float cx = fxy[b3]   - fxy[b2];
            const float cy = fxy[b3+2] - fxy[b2+2];
            const float cz = fz[z3]    - fz[z2];

            const float p1x = ay * bz - az * by;
            const float p1y = az * bx - ax * bz;
            const float p1z = ax * by - ay * bx;
            const float p2x = by * cz - bz * cy;
            const float p2y = bz * cx - bx * cz;
            const float p2z = bx * cy - by * cx;

            const float n1sq  = fmaf(p1x, p1x, fmaf(p1y, p1y, p1z * p1z));
            const float n2sq  = fmaf(p2x, p2x, fmaf(p2y, p2y, p2z * p2z));
            const float inv12 = rsqrtf(n1sq * n2sq);

            float* oo = o0 + fr * o1off;
            const float dp = fmaf(p1x, p2x, fmaf(p1y, p2y, p1z * p2z));
            oo[OFF_DCOS + d] = dp * inv12;

            const float qx = p1y * p2z - p1z * p2y;
            const float qy = p1z * p2x - p1x * p2z;
            const float qz = p1x * p2y - p1y * p2x;
            const float num  = fmaf(qx, bx, fmaf(qy, by, qz * bz));
            const float bnsq = fmaf(bx, bx, fmaf(by, by, bz * bz));
            oo[OFF_DSIN + d] = num * inv12 * rsqrtf(bnsq);
        }
    }
}

extern "C" void kernel_launch(void* const* d_in, const int* in_sizes, int n_in,
                              void* d_out, int out_size)
{
    const float* data = (const float*)d_in[0];
    float* out = (float*)d_out;
    const int n_frames = in_sizes[0] / (NB * 3);
    const int n_blocks = (n_frames + 1) / 2;

    protein_feat_kernel<<<n_blocks, NTHREADS>>>(data, out, n_frames);
}

// round 14
// speedup vs baseline: 1.2358x; 1.0693x over previous
#include <cuda_runtime.h>
#include <stdint.h>
#include <math.h>

#define NB        50
#define NF_DIST   1225
#define NF_ANG    48
#define NF_DIH    47
#define NFEAT     (NF_DIST + NF_ANG + 2*NF_DIH)   // 1367

#define OFF_ANG   NF_DIST                 // 1225
#define OFF_DCOS  (NF_DIST + NF_ANG)      // 1273
#define OFF_DSIN  (OFF_DCOS + NF_DIH)     // 1320

// 7 groups of 7 rows: inc0 = 7g+1, tasks per group = 50 - inc0. Total 196.
#define NTASK     196
#define T_ANG0    196
#define T_DIH0    (T_ANG0 + NF_ANG)       // 244
#define T_END     (T_DIH0 + NF_DIH)       // 291
#define NTHREADS  320

struct TaskTable { uint32_t v[NTASK]; };
constexpr TaskTable make_tasks() {
    TaskTable t{};
    int n = 0;
    for (int g = 0; g < 7; ++g) {
        const int inc0 = 7 * g + 1;
        const int f0   = (inc0 - 1) * (100 - inc0) / 2;
        for (int i = 0; i < NB - inc0; ++i)
            t.v[n++] = (uint32_t)(i | (inc0 << 6) | (f0 << 12));
    }
    return t;
}
__device__ constexpr TaskTable g_tasks = make_tasks();

typedef unsigned long long u64;
__device__ __forceinline__ u64 f2_pack(float lo, float hi) {
    u64 r; asm("mov.b64 %0, {%1, %2};" : "=l"(r) : "f"(lo), "f"(hi)); return r;
}
__device__ __forceinline__ void f2_unpack(float& lo, float& hi, u64 v) {
    asm("mov.b64 {%0, %1}, %2;" : "=f"(lo), "=f"(hi) : "l"(v));
}
__device__ __forceinline__ u64 f2_add(u64 a, u64 b) {
    u64 r; asm("add.rn.f32x2 %0, %1, %2;" : "=l"(r) : "l"(a), "l"(b)); return r;
}
__device__ __forceinline__ u64 f2_mul(u64 a, u64 b) {
    u64 r; asm("mul.rn.f32x2 %0, %1, %2;" : "=l"(r) : "l"(a), "l"(b)); return r;
}
__device__ __forceinline__ u64 f2_fma(u64 a, u64 b, u64 c) {
    u64 r; asm("fma.rn.f32x2 %0, %1, %2, %3;" : "=l"(r) : "l"(a), "l"(b), "l"(c)); return r;
}
__device__ __forceinline__ float fast_sqrt(float x) {
    float r; asm("sqrt.approx.f32 %0, %1;" : "=f"(r) : "f"(x)); return r;
}

// One distance iteration with compile-time immediate offsets. Template
// recursion guarantees "n" constraints see true constants.
template<int K>
__device__ __forceinline__ void dist_iters(int j0, int rl, unsigned aXY,
                                           unsigned aZ, float* po,
                                           u64 nax, u64 nay, u64 naz)
{
    if (j0 + K < NB) {
        u64 bx, by, bz;
        asm("ld.shared.v2.b64 {%0, %1}, [%2 + %3];"
            : "=l"(bx), "=l"(by) : "r"(aXY), "n"(16 * K));
        asm("ld.shared.b64 %0, [%1 + %2];"
            : "=l"(bz) : "r"(aZ), "n"(8 * K));

        const u64 dx = f2_add(bx, nax);
        const u64 dy = f2_add(by, nay);
        const u64 dz = f2_add(bz, naz);

        const u64 s2 = f2_fma(dx, dx, f2_fma(dy, dy, f2_mul(dz, dz)));
        float s0, s1; f2_unpack(s0, s1, s2);

        po[0]     = fast_sqrt(s0);
        po[NFEAT] = fast_sqrt(s1);      // immediate offset: frame1 = frame0+1
    }
    if constexpr (K < 6)
        dist_iters<K + 1>(j0, rl, aXY, aZ, po + (rl - K), nax, nay, naz);
}

__global__ __launch_bounds__(NTHREADS, 6)
void protein_feat_kernel2(const float* __restrict__ data,
                          float* __restrict__ out)
{
    // Per bead: sXY = {x_f0, x_f1, y_f0, y_f1}, sZ = {z_f0, z_f1}
    __shared__ float4 sXY[NB];
    __shared__ float2 sZ[NB];

    const int tid    = threadIdx.x;
    const int frame0 = blockIdx.x * 2;       // always a full pair (hot kernel)

    if (tid < 300) {
        const int fr = (tid >= 150);
        const int r  = tid - 150 * fr;
        const int bd = r / 3;
        const int c  = r - 3 * bd;
        const float v = data[(size_t)(frame0 + fr) * (NB * 3) + r];
        if (c == 2) ((float*)&sZ[bd])[fr]        = v;
        else        ((float*)&sXY[bd])[2*c + fr] = v;
    }
    __syncthreads();

    float* o0 = out + (size_t)frame0 * NFEAT;

    if (tid < NTASK) {
        const uint32_t tv = g_tasks.v[tid];
        const int i       = tv & 63;
        const int inc0    = (tv >> 6) & 63;
        const int rl      = NB - inc0;
        const int f0      = (int)(tv >> 12) + i;
        const int j0      = i + inc0;

        // negated A bead, packed (both frames)
        const float4 Axy = sXY[i];
        const float2 Az  = sZ[i];
        const u64 nax = f2_pack(-Axy.x, -Axy.y);
        const u64 nay = f2_pack(-Axy.z, -Axy.w);
        const u64 naz = f2_pack(-Az.x,  -Az.y);

        const unsigned aXY = (unsigned)__cvta_generic_to_shared(&sXY[j0]);
        const unsigned aZ  = (unsigned)__cvta_generic_to_shared(&sZ[j0]);

        dist_iters<0>(j0, rl, aXY, aZ, o0 + f0, nax, nay, naz);
    }
    else if (tid < T_DIH0) {
        // ---- angles, both frames (scalar) ----
        const int a = tid - T_ANG0;
        const float* fxy = (const float*)sXY;   // [4b+0/1]=x, [4b+2/3]=y
        const float* fz  = (const float*)sZ;    // [2b+fr]=z
        #pragma unroll
        for (int fr = 0; fr < 2; ++fr) {
            const int b0 = 4*a + fr, b1 = b0 + 4, b2 = b0 + 8;
            const int z0 = 2*a + fr, z1 = z0 + 2, z2 = z0 + 4;
            const float b1x = fxy[b0]   - fxy[b1];
            const float b1y = fxy[b0+2] - fxy[b1+2];
            const float b1z = fz[z0]    - fz[z1];
            const float b2x = fxy[b2]   - fxy[b1];
            const float b2y = fxy[b2+2] - fxy[b1+2];
            const float b2z = fz[z2]    - fz[z1];

            const float dot = fmaf(b1x, b2x, fmaf(b1y, b2y, b1z * b2z));
            const float n1  = fmaf(b1x, b1x, fmaf(b1y, b1y, b1z * b1z));
            const float n2  = fmaf(b2x, b2x, fmaf(b2y, b2y, b2z * b2z));
            float ct = dot * rsqrtf(n1 * n2);
            ct = fminf(1.0f, fmaxf(-1.0f, ct));
            o0[fr * NFEAT + OFF_ANG + a] = acosf(ct);
        }
    }
    else if (tid < T_END) {
        // ---- dihedrals (cos+sin fused), both frames (scalar) ----
        const int d = tid - T_DIH0;
        const float* fxy = (const float*)sXY;
        const float* fz  = (const float*)sZ;
        #pragma unroll
        for (int fr = 0; fr < 2; ++fr) {
            const int b0 = 4*d + fr, b1 = b0 + 4, b2 = b0 + 8, b3 = b0 + 12;
            const int z0 = 2*d + fr, z1 = z0 + 2, z2 = z0 + 4, z3 = z0 + 6;

            const float ax = fxy[b1]   - fxy[b0];
            const float ay = fxy[b1+2] - fxy[b0+2];
            const float az = fz[z1]    - fz[z0];
            const float bx = fxy[b2]   - fxy[b1];
            const float by = fxy[b2+2] - fxy[b1+2];
            const float bz = fz[z2]    - fz[z1];
            const float cx = fxy[b3]   - fxy[b2];
            const float cy = fxy[b3+2] - fxy[b2+2];
            const float cz = fz[z3]    - fz[z2];

            const float p1x = ay * bz - az * by;
            const float p1y = az * bx - ax * bz;
            const float p1z = ax * by - ay * bx;
            const float p2x = by * cz - bz * cy;
            const float p2y = bz * cx - bx * cz;
            const float p2z = bx * cy - by * cx;

            const float n1sq  = fmaf(p1x, p1x, fmaf(p1y, p1y, p1z * p1z));
            const float n2sq  = fmaf(p2x, p2x, fmaf(p2y, p2y, p2z * p2z));
            const float inv12 = rsqrtf(n1sq * n2sq);

            float* oo = o0 + fr * NFEAT;
            const float dp = fmaf(p1x, p2x, fmaf(p1y, p2y, p1z * p2z));
            oo[OFF_DCOS + d] = dp * inv12;

            const float qx = p1y * p2z - p1z * p2y;
            const float qy = p1z * p2x - p1x * p2z;
            const float qz = p1x * p2y - p1y * p2x;
            const float num  = fmaf(qx, bx, fmaf(qy, by, qz * bz));
            const float bnsq = fmaf(bx, bx, fmaf(by, by, bz * bz));
            oo[OFF_DSIN + d] = num * inv12 * rsqrtf(bnsq);
        }
    }
}

// ---- tail: one frame (only launched when n_frames is odd) ----
__global__ __launch_bounds__(NTHREADS)
void protein_feat_kernel1(const float* __restrict__ data,
                          float* __restrict__ out,
                          int frame)
{
    __shared__ float tx[NB], ty[NB], tz[NB];

    const int tid = threadIdx.x;
    const float* p = data + (size_t)frame * NB * 3;
    if (tid < NB * 3) {
        const int bd = tid / 3, c = tid - 3 * bd;
        const float v = p[tid];
        if (c == 0) tx[bd] = v; else if (c == 1) ty[bd] = v; else tz[bd] = v;
    }
    __syncthreads();

    float* o = out + (size_t)frame * NFEAT;

    if (tid < NTASK) {
        const uint32_t tv = g_tasks.v[tid];
        const int i    = tv & 63;
        const int inc0 = (tv >> 6) & 63;
        const int rl   = NB - inc0;
        int f          = (int)(tv >> 12) + i;
        int j          = i + inc0;
        const float ax = tx[i], ay = ty[i], az = tz[i];

        #pragma unroll
        for (int k = 0; k < 7; ++k) {
            if (j < NB) {
                const float dx = tx[j] - ax;
                const float dy = ty[j] - ay;
                const float dz = tz[j] - az;
                o[f] = fast_sqrt(fmaf(dx, dx, fmaf(dy, dy, dz * dz)));
            }
            f += rl - k;
            ++j;
        }
    }
    else if (tid < T_DIH0) {
        const int a = tid - T_ANG0;
        const float b1x = tx[a] - tx[a+1], b1y = ty[a] - ty[a+1], b1z = tz[a] - tz[a+1];
        const float b2x = tx[a+2] - tx[a+1], b2y = ty[a+2] - ty[a+1], b2z = tz[a+2] - tz[a+1];
        const float dot = fmaf(b1x, b2x, fmaf(b1y, b2y, b1z * b2z));
        const float n1  = fmaf(b1x, b1x, fmaf(b1y, b1y, b1z * b1z));
        const float n2  = fmaf(b2x, b2x, fmaf(b2y, b2y, b2z * b2z));
        float ct = dot * rsqrtf(n1 * n2);
        ct = fminf(1.0f, fmaxf(-1.0f, ct));
        o[OFF_ANG + a] = acosf(ct);
    }
    else if (tid < T_END) {
        const int d = tid - T_DIH0;
        const float ax = tx[d+1]-tx[d], ay = ty[d+1]-ty[d], az = tz[d+1]-tz[d];
        const float bx = tx[d+2]-tx[d+1], by = ty[d+2]-ty[d+1], bz = tz[d+2]-tz[d+1];
        const float cx = tx[d+3]-tx[d+2], cy = ty[d+3]-ty[d+2], cz = tz[d+3]-tz[d+2];

        const float p1x = ay*bz - az*by, p1y = az*bx - ax*bz, p1z = ax*by - ay*bx;
        const float p2x = by*cz - bz*cy, p2y = bz*cx - bx*cz, p2z = bx*cy - by*cx;

        const float n1sq  = fmaf(p1x, p1x, fmaf(p1y, p1y, p1z * p1z));
        const float n2sq  = fmaf(p2x, p2x, fmaf(p2y, p2y, p2z * p2z));
        const float inv12 = rsqrtf(n1sq * n2sq);

        const float dp = fmaf(p1x, p2x, fmaf(p1y, p2y, p1z * p2z));
        o[OFF_DCOS + d] = dp * inv12;

        const float qx = p1y*p2z - p1z*p2y, qy = p1z*p2x - p1x*p2z, qz = p1x*p2y - p1y*p2x;
        const float num  = fmaf(qx, bx, fmaf(qy, by, qz * bz));
        const float bnsq = fmaf(bx, bx, fmaf(by, by, bz * bz));
        o[OFF_DSIN + d] = num * inv12 * rsqrtf(bnsq);
    }
}

extern "C" void kernel_launch(void* const* d_in, const int* in_sizes, int n_in,
                              void* d_out, int out_size)
{
    const float* data = (const float*)d_in[0];
    float* out = (float*)d_out;
    const int n_frames = in_sizes[0] / (NB * 3);
    const int npairs   = n_frames / 2;

    if (npairs > 0)
        protein_feat_kernel2<<<npairs, NTHREADS>>>(data, out);
    if (n_frames & 1)
        protein_feat_kernel1<<<1, NTHREADS>>>(data, out, n_frames - 1);
}